// round 2
// baseline (speedup 1.0000x reference)
#include <cuda_runtime.h>
#include <cuda_bf16.h>

// Problem constants
#define BB 1024
#define RR 8
#define CC 1024
#define DD 16384
#define KK 32
#define NEX 40      // extracted candidates per row
#define THRC 48     // threshold suffix-count (>= NEX with margin)
#define WIN 1e-3f   // fp64 refinement window around fast rank-32 value

// ---------------- device scratch (allocation-free rule: __device__ globals) ---
__device__ float g_h[(size_t)BB * RR * DD];     // 512 MB: encoder pre-activations
__device__ float g_dwT[(size_t)RR * DD * CC];   // 512 MB: decoder_w transposed [R,D,C]
__device__ float g_topv[BB * RR * KK];
__device__ int   g_topi[BB * RR * KK];

// ---------------- kernel 1: transpose decoder_w [R,C,D] -> [R,D,C] ------------
__global__ void transpose_dw(const float* __restrict__ dw) {
    __shared__ float tile[32][33];
    int r  = blockIdx.z;
    int d0 = blockIdx.x * 32;
    int c0 = blockIdx.y * 32;
    const float* src = dw   + (size_t)r * CC * DD;
    float*       dst = g_dwT + (size_t)r * DD * CC;
    int tx = threadIdx.x, ty = threadIdx.y;  // 32 x 8
#pragma unroll
    for (int i = 0; i < 32; i += 8)
        tile[ty + i][tx] = src[(size_t)(c0 + ty + i) * DD + d0 + tx];
    __syncthreads();
#pragma unroll
    for (int i = 0; i < 32; i += 8)
        dst[(size_t)(d0 + ty + i) * CC + c0 + tx] = tile[tx][ty + i];
}

// ---------------- kernel 2: encode GEMM (fp32) --------------------------------
// h[b,r,d] = sum_c (x[b,r,c] - db[r,c]) * ew[r,d,c] + eb[r,d]
#define BM 128
#define BN 128
#define BK 16
__global__ __launch_bounds__(256) void encode_gemm(const float* __restrict__ x,
                                                   const float* __restrict__ ew,
                                                   const float* __restrict__ eb,
                                                   const float* __restrict__ db) {
    __shared__ float As[BK][BM];
    __shared__ float Bs[BK][BN];

    int r    = blockIdx.z;
    int nBlk = blockIdx.x;
    int mBlk = blockIdx.y;
    int tid  = threadIdx.x;

    const float* A   = x  + (size_t)r * CC;
    const float* Bm  = ew + (size_t)r * DD * CC;
    const float* dbr = db + r * CC;

    int lr = tid >> 2;
    int lc = (tid & 3) * 4;
    int tm = (tid >> 4) * 8;
    int tn = (tid & 15) * 8;

    float acc[8][8];
#pragma unroll
    for (int i = 0; i < 8; i++)
#pragma unroll
        for (int j = 0; j < 8; j++) acc[i][j] = 0.f;

    for (int k0 = 0; k0 < CC; k0 += BK) {
#pragma unroll
        for (int s = 0; s < BM; s += 64) {
            int m = mBlk * BM + lr + s;
            float4 av  = *(const float4*)(A + (size_t)m * (RR * CC) + k0 + lc);
            float4 dbv = *(const float4*)(dbr + k0 + lc);
            As[lc + 0][lr + s] = av.x - dbv.x;
            As[lc + 1][lr + s] = av.y - dbv.y;
            As[lc + 2][lr + s] = av.z - dbv.z;
            As[lc + 3][lr + s] = av.w - dbv.w;
            int n = nBlk * BN + lr + s;
            float4 bv = *(const float4*)(Bm + (size_t)n * CC + k0 + lc);
            Bs[lc + 0][lr + s] = bv.x;
            Bs[lc + 1][lr + s] = bv.y;
            Bs[lc + 2][lr + s] = bv.z;
            Bs[lc + 3][lr + s] = bv.w;
        }
        __syncthreads();
#pragma unroll
        for (int kk = 0; kk < BK; kk++) {
            float a[8], b[8];
            *(float4*)(a)     = *(const float4*)&As[kk][tm];
            *(float4*)(a + 4) = *(const float4*)&As[kk][tm + 4];
            *(float4*)(b)     = *(const float4*)&Bs[kk][tn];
            *(float4*)(b + 4) = *(const float4*)&Bs[kk][tn + 4];
#pragma unroll
            for (int i = 0; i < 8; i++)
#pragma unroll
                for (int j = 0; j < 8; j++)
                    acc[i][j] += a[i] * b[j];
        }
        __syncthreads();
    }

    const float* ebr = eb + (size_t)r * DD;
    int nbase = nBlk * BN + tn;
#pragma unroll
    for (int i = 0; i < 8; i++) {
        size_t m = (size_t)(mBlk * BM + tm + i);
        float* hp = g_h + m * (RR * DD) + (size_t)r * DD + nbase;
#pragma unroll
        for (int j = 0; j < 8; j += 4) {
            float4 v;
            v.x = acc[i][j + 0] + ebr[nbase + j + 0];
            v.y = acc[i][j + 1] + ebr[nbase + j + 1];
            v.z = acc[i][j + 2] + ebr[nbase + j + 2];
            v.w = acc[i][j + 3] + ebr[nbase + j + 3];
            *(float4*)(hp + j) = v;
        }
    }
}

// ---------------- kernel 3: exact top-32 with fp64 boundary refinement --------
#define NBINS 4096
#define MAXCAND 2048
__global__ __launch_bounds__(256) void topk_kernel(const float* __restrict__ x,
                                                   const float* __restrict__ ew,
                                                   const float* __restrict__ eb,
                                                   const float* __restrict__ db) {
    extern __shared__ unsigned int sh[];
    unsigned int* keys = sh;                         // 16384
    unsigned int* hist = sh + DD;                    // 4096
    unsigned long long* cand =
        (unsigned long long*)(hist + NBINS);         // 2048

    __shared__ unsigned int part[256];
    __shared__ unsigned int s_thrbin, s_cnt;
    __shared__ unsigned long long wmax[8];
    __shared__ unsigned long long s_max;
    __shared__ float sval[NEX];
    __shared__ int   sidx[NEX];
    __shared__ double dv[NEX];
    __shared__ double red[256];

    int row = blockIdx.x;            // row = b*RR + r
    int b_  = row >> 3;
    int r_  = row & 7;
    int tid = threadIdx.x;
    const float* hp = g_h + (size_t)row * DD;

    for (int i = tid; i < NBINS; i += 256) hist[i] = 0;
    if (tid == 0) s_cnt = 0;
    __syncthreads();

    for (int i = tid; i < DD; i += 256) {
        unsigned int bb = __float_as_uint(hp[i]);
        unsigned int u = (bb & 0x80000000u) ? ~bb : (bb | 0x80000000u);
        keys[i] = u;
        atomicAdd(&hist[u >> 20], 1u);
    }
    __syncthreads();

    // find smallest bin T with suffix count >= THRC
    unsigned int psum = 0;
#pragma unroll
    for (int j = 0; j < 16; j++) psum += hist[tid * 16 + j];
    part[tid] = psum;
    __syncthreads();

    if (tid == 0) {
        unsigned int acc = 0;
        int seg = 255;
        for (; seg > 0; seg--) {
            if (acc + part[seg] >= THRC) break;
            acc += part[seg];
        }
        unsigned int a2 = acc;
        int T = seg * 16;
        for (int b2 = seg * 16 + 15; b2 >= seg * 16; b2--) {
            if (a2 + hist[b2] >= THRC) { T = b2; break; }
            a2 += hist[b2];
        }
        s_thrbin = (unsigned int)T;
    }
    __syncthreads();

    unsigned int T = s_thrbin;
    for (int i = tid; i < DD; i += 256) {
        if ((keys[i] >> 20) >= T) {
            unsigned int p = atomicAdd(&s_cnt, 1u);
            if (p < MAXCAND)
                cand[p] = ((unsigned long long)keys[i] << 32) |
                          (unsigned long long)(DD - 1 - i);   // ties -> lower i wins
        }
    }
    __syncthreads();

    unsigned int M = s_cnt < MAXCAND ? s_cnt : MAXCAND;
    int lane = tid & 31, warp = tid >> 5;

    // extract top NEX (exact over fast fp32 h)
    for (int t = 0; t < NEX; t++) {
        unsigned long long lm = 0ull;
        for (unsigned int i = tid; i < M; i += 256) {
            unsigned long long v = cand[i];
            if (v > lm) lm = v;
        }
#pragma unroll
        for (int off = 16; off > 0; off >>= 1) {
            unsigned long long o = __shfl_xor_sync(0xffffffffu, lm, off);
            if (o > lm) lm = o;
        }
        if (lane == 0) wmax[warp] = lm;
        __syncthreads();
        if (tid == 0) {
            unsigned long long m = wmax[0];
#pragma unroll
            for (int w = 1; w < 8; w++) if (wmax[w] > m) m = wmax[w];
            s_max = m;
        }
        __syncthreads();
        unsigned long long m = s_max;
        for (unsigned int i = tid; i < M; i += 256)
            if (cand[i] == m) cand[i] = 0ull;
        if (tid == 0) {
            unsigned int u  = (unsigned int)(m >> 32);
            int idx = DD - 1 - (int)(m & 0xffffffffull);
            unsigned int fb = (u & 0x80000000u) ? (u & 0x7fffffffu) : ~u;
            sval[t] = __uint_as_float(fb);
            sidx[t] = idx;
        }
        __syncthreads();
    }

    // fp64 refinement for candidates near the rank-32 boundary
    float vb = sval[KK - 1];
    const float* xr  = x  + (size_t)b_ * (RR * CC) + (size_t)r_ * CC;
    const float* dbr = db + r_ * CC;
    const float* ewr = ew + (size_t)r_ * DD * CC;
    for (int j = 0; j < NEX; j++) {
        if (fabsf(sval[j] - vb) <= WIN) {       // uniform predicate (smem value)
            int d = sidx[j];
            const float* wv = ewr + (size_t)d * CC;
            double acc = 0.0;
            for (int c = tid; c < CC; c += 256)
                acc += ((double)xr[c] - (double)dbr[c]) * (double)wv[c];
            red[tid] = acc;
            __syncthreads();
            for (int off2 = 128; off2 > 0; off2 >>= 1) {
                if (tid < off2) red[tid] += red[tid + off2];
                __syncthreads();
            }
            if (tid == 0)
                dv[j] = red[0] + (double)eb[(size_t)r_ * DD + d];
            __syncthreads();
        } else if (tid == 0) {
            dv[j] = (double)sval[j];
        }
    }
    __syncthreads();

    // re-rank (value desc, index asc) and emit top 32
    if (tid == 0) {
        for (int i = 1; i < NEX; i++) {
            double v = dv[i]; int id = sidx[i];
            int j = i - 1;
            while (j >= 0 && (dv[j] < v || (dv[j] == v && sidx[j] > id))) {
                dv[j + 1] = dv[j]; sidx[j + 1] = sidx[j]; j--;
            }
            dv[j + 1] = v; sidx[j + 1] = id;
        }
        for (int t = 0; t < KK; t++) {
            g_topv[row * KK + t] = fmaxf((float)dv[t], 0.f);
            g_topi[row * KK + t] = sidx[t];
        }
    }
}

// ---------------- kernel 4: sparse decode -------------------------------------
__global__ __launch_bounds__(256) void decode_kernel(const float* __restrict__ db,
                                                     float* __restrict__ out) {
    __shared__ float sv[KK];
    __shared__ int   si[KK];
    int b = blockIdx.x, r = blockIdx.y;
    int row = b * RR + r;
    int tid = threadIdx.x;
    if (tid < KK) {
        sv[tid] = g_topv[row * KK + tid];
        si[tid] = g_topi[row * KK + tid];
    }
    __syncthreads();

    const float* base = g_dwT + (size_t)r * DD * CC;
    float4 acc = *(const float4*)(db + r * CC + tid * 4);
#pragma unroll 8
    for (int t = 0; t < KK; t++) {
        float v = sv[t];
        float4 w = *(const float4*)(base + (size_t)si[t] * CC + tid * 4);
        acc.x += v * w.x;
        acc.y += v * w.y;
        acc.z += v * w.z;
        acc.w += v * w.w;
    }
    *(float4*)(out + (size_t)b * (RR * CC) + r * CC + tid * 4) = acc;
}

// ---------------- launch -------------------------------------------------------
extern "C" void kernel_launch(void* const* d_in, const int* in_sizes, int n_in,
                              void* d_out, int out_size) {
    const float* x  = (const float*)d_in[0];
    const float* ew = (const float*)d_in[1];
    const float* eb = (const float*)d_in[2];
    const float* dw = (const float*)d_in[3];
    const float* db = (const float*)d_in[4];
    float* out = (float*)d_out;

    cudaFuncSetAttribute(topk_kernel,
                         cudaFuncAttributeMaxDynamicSharedMemorySize, 100352);

    transpose_dw<<<dim3(DD / 32, CC / 32, RR), dim3(32, 8)>>>(dw);
    encode_gemm<<<dim3(DD / BN, BB / BM, RR), 256>>>(x, ew, eb, db);
    topk_kernel<<<BB * RR, 256, (DD + NBINS) * 4 + MAXCAND * 8>>>(x, ew, eb, db);
    decode_kernel<<<dim3(BB, RR), 256>>>(db, out);
}

// round 4
// speedup vs baseline: 1.9853x; 1.9853x over previous
#include <cuda_runtime.h>
#include <cuda_bf16.h>
#include <cstdint>

// Problem constants
#define BB 1024
#define RR 8
#define CC 1024
#define DD 16384
#define KK 32
#define NEX 48
#define THRC 56

// ---------------- device scratch ----------------------------------------------
__device__ float g_h[(size_t)BB * RR * DD];
__device__ float g_dwT[(size_t)RR * DD * CC];
__device__ float g_topv[BB * RR * KK];
__device__ int   g_topi[BB * RR * KK];
__device__ __nv_bfloat16 g_xb[(size_t)BB * RR * CC];
__device__ __nv_bfloat16 g_ewb[(size_t)RR * DD * CC];

__device__ __forceinline__ uint32_t smem_u32(const void* p) {
    uint32_t a;
    asm("{ .reg .u64 t; cvta.to.shared.u64 t, %1; cvt.u32.u64 %0, t; }" : "=r"(a) : "l"(p));
    return a;
}

// ---------------- kernel 0a: x - db -> bf16 ------------------------------------
__global__ __launch_bounds__(256) void conv_x(const float* __restrict__ x,
                                              const float* __restrict__ db) {
    size_t i = (size_t)blockIdx.x * 256 + threadIdx.x;   // group of 4 elems
    size_t e = i * 4;
    int c = (int)(e & (CC - 1));
    int r = (int)((e >> 10) & 7);
    float4 xv = ((const float4*)x)[i];
    float4 dv = *(const float4*)(db + r * CC + c);
    unsigned short h[4];
    h[0] = __bfloat16_as_ushort(__float2bfloat16(xv.x - dv.x));
    h[1] = __bfloat16_as_ushort(__float2bfloat16(xv.y - dv.y));
    h[2] = __bfloat16_as_ushort(__float2bfloat16(xv.z - dv.z));
    h[3] = __bfloat16_as_ushort(__float2bfloat16(xv.w - dv.w));
    uint2 u = {(uint32_t)h[0] | ((uint32_t)h[1] << 16),
               (uint32_t)h[2] | ((uint32_t)h[3] << 16)};
    ((uint2*)g_xb)[i] = u;
}

// ---------------- kernel 0b: ew -> bf16 -----------------------------------------
__global__ __launch_bounds__(256) void conv_ew(const float* __restrict__ ew) {
    size_t i = (size_t)blockIdx.x * 256 + threadIdx.x;
    float4 v = ((const float4*)ew)[i];
    unsigned short h[4];
    h[0] = __bfloat16_as_ushort(__float2bfloat16(v.x));
    h[1] = __bfloat16_as_ushort(__float2bfloat16(v.y));
    h[2] = __bfloat16_as_ushort(__float2bfloat16(v.z));
    h[3] = __bfloat16_as_ushort(__float2bfloat16(v.w));
    uint2 u = {(uint32_t)h[0] | ((uint32_t)h[1] << 16),
               (uint32_t)h[2] | ((uint32_t)h[3] << 16)};
    ((uint2*)g_ewb)[i] = u;
}

// ---------------- kernel 1: transpose decoder_w [R,C,D] -> [R,D,C] -------------
__global__ void transpose_dw(const float* __restrict__ dw) {
    __shared__ float tile[32][33];
    int r  = blockIdx.z;
    int d0 = blockIdx.x * 32;
    int c0 = blockIdx.y * 32;
    const float* src = dw   + (size_t)r * CC * DD;
    float*       dst = g_dwT + (size_t)r * DD * CC;
    int tx = threadIdx.x, ty = threadIdx.y;
#pragma unroll
    for (int i = 0; i < 32; i += 8)
        tile[ty + i][tx] = src[(size_t)(c0 + ty + i) * DD + d0 + tx];
    __syncthreads();
#pragma unroll
    for (int i = 0; i < 32; i += 8)
        dst[(size_t)(d0 + ty + i) * CC + c0 + tx] = tile[tx][ty + i];
}

// ---------------- kernel 2: encode GEMM via mma.sync (bf16, fp32 accum) --------
// h[m, r, d] = sum_c xb[m,r,c] * ewb[r,d,c] + eb[r,d]
// CTA tile 128(M) x 128(N), BK=32, 4-stage cp.async pipeline.
#define GBK 32
#define KT (CC / GBK)          // 32
#define STG 4
#define ATILE_B 8192           // 128 * 32 * 2
#define STAGE_B 16384          // A + B tile

__device__ __forceinline__ void ldm_x4(uint32_t addr, uint32_t& r0, uint32_t& r1,
                                       uint32_t& r2, uint32_t& r3) {
    asm volatile("ldmatrix.sync.aligned.m8n8.x4.shared.b16 {%0,%1,%2,%3}, [%4];"
                 : "=r"(r0), "=r"(r1), "=r"(r2), "=r"(r3) : "r"(addr));
}
__device__ __forceinline__ void mma16816(float* c, uint32_t a0, uint32_t a1,
                                         uint32_t a2, uint32_t a3,
                                         uint32_t b0, uint32_t b1) {
    asm volatile(
        "mma.sync.aligned.m16n8k16.row.col.f32.bf16.bf16.f32 "
        "{%0,%1,%2,%3}, {%4,%5,%6,%7}, {%8,%9}, {%0,%1,%2,%3};"
        : "+f"(c[0]), "+f"(c[1]), "+f"(c[2]), "+f"(c[3])
        : "r"(a0), "r"(a1), "r"(a2), "r"(a3), "r"(b0), "r"(b1));
}

__global__ __launch_bounds__(256, 2) void encode_gemm_mma(const float* __restrict__ eb) {
    extern __shared__ char smem[];
    uint32_t sb = smem_u32(smem);

    int tid = threadIdx.x, lane = tid & 31, wid = tid >> 5;
    int warp_m = wid >> 2;           // 0..1 -> 64 rows
    int warp_n = wid & 3;            // 0..3 -> 32 cols
    int mBase = blockIdx.x * 128;
    int nBase = blockIdx.y * 128;
    int r     = blockIdx.z;

    const __nv_bfloat16* Bb = g_ewb + (size_t)r * DD * CC;

    // cp.async slot precompute: uid = tid + i*256 (i<2: A, else B)
    uint32_t soff[4];
    const __nv_bfloat16* gbase[4];
#pragma unroll
    for (int i = 0; i < 4; i++) {
        int uid = tid + i * 256;
        int row = (uid & 511) >> 2;
        int u   = uid & 3;
        bool isA = uid < 512;
        soff[i] = (isA ? 0u : (uint32_t)ATILE_B) +
                  (uint32_t)(row * 64 + ((u ^ ((row >> 1) & 3)) << 4));
        gbase[i] = isA ? (g_xb + ((size_t)(mBase + row) * RR + r) * CC + u * 8)
                       : (Bb + (size_t)(nBase + row) * CC + u * 8);
    }

    auto issue_stage = [&](int kt, int s) {
        uint32_t sbase = sb + s * STAGE_B;
        int k0 = kt * GBK;
#pragma unroll
        for (int i = 0; i < 4; i++) {
            uint32_t sa = sbase + soff[i];
            const void* g = (const void*)(gbase[i] + k0);
            asm volatile("cp.async.cg.shared.global [%0], [%1], 16;"
                         :: "r"(sa), "l"(g));
        }
        asm volatile("cp.async.commit_group;");
    };

    // prologue
#pragma unroll
    for (int s = 0; s < STG - 1; s++) issue_stage(s, s);

    float acc[16][4];
#pragma unroll
    for (int i = 0; i < 16; i++)
#pragma unroll
        for (int j = 0; j < 4; j++) acc[i][j] = 0.f;

    // ldmatrix address precompute (per k-step updated by unit selection)
    int arow = warp_m * 64 + (lane & 15);            // + mf*16
    int ab   = (lane >> 4) & 1;                      // A unit low bit
    int nrow = warp_n * 32 + ((lane >> 4) << 3) + (lane & 7);  // + nfp*16
    int bb_  = (lane >> 3) & 1;                      // B unit low bit

    for (int kt = 0; kt < KT; kt++) {
        asm volatile("cp.async.wait_group %0;" :: "n"(STG - 2));
        __syncthreads();
        if (kt + STG - 1 < KT) issue_stage(kt + STG - 1, (kt + STG - 1) & (STG - 1));
        else asm volatile("cp.async.commit_group;");

        uint32_t sA = sb + (kt & (STG - 1)) * STAGE_B;
        uint32_t sB = sA + ATILE_B;

#pragma unroll
        for (int ks = 0; ks < 2; ks++) {
            // B frags: 2 x ldmatrix.x4 cover 4 n-frags
            uint32_t bfr[8];
#pragma unroll
            for (int nfp = 0; nfp < 2; nfp++) {
                int rown = nrow + nfp * 16;
                int unit = ks * 2 + bb_;
                uint32_t addr = sB + rown * 64 + ((unit ^ ((rown >> 1) & 3)) << 4);
                ldm_x4(addr, bfr[nfp * 4 + 0], bfr[nfp * 4 + 1],
                             bfr[nfp * 4 + 2], bfr[nfp * 4 + 3]);
            }
#pragma unroll
            for (int mf = 0; mf < 4; mf++) {
                int rowm = arow + mf * 16;
                int unit = ks * 2 + ab;
                uint32_t addr = sA + rowm * 64 + ((unit ^ ((rowm >> 1) & 3)) << 4);
                uint32_t a0, a1, a2, a3;
                ldm_x4(addr, a0, a1, a2, a3);
#pragma unroll
                for (int nf = 0; nf < 4; nf++)
                    mma16816(acc[mf * 4 + nf], a0, a1, a2, a3,
                             bfr[nf * 2], bfr[nf * 2 + 1]);
            }
        }
        __syncthreads();
    }

    // epilogue: add eb, store fp32 h
    int trow = lane >> 2;            // 0..7
    int tcol = (lane & 3) * 2;
    const float* ebr = eb + (size_t)r * DD;
#pragma unroll
    for (int mf = 0; mf < 4; mf++) {
#pragma unroll
        for (int nf = 0; nf < 4; nf++) {
            int m = mBase + warp_m * 64 + mf * 16 + trow;
            int d = nBase + warp_n * 32 + nf * 8 + tcol;
            float2 ebv = *(const float2*)(ebr + d);
            float* h0 = g_h + (size_t)m * (RR * DD) + (size_t)r * DD + d;
            float* h1 = h0 + 8 * (size_t)(RR * DD);
            float2 v0 = {acc[mf * 4 + nf][0] + ebv.x, acc[mf * 4 + nf][1] + ebv.y};
            float2 v1 = {acc[mf * 4 + nf][2] + ebv.x, acc[mf * 4 + nf][3] + ebv.y};
            *(float2*)h0 = v0;
            *(float2*)h1 = v1;
        }
    }
}

// ---------------- kernel 3: top-32 with fp64 refinement of all candidates ------
#define NBINS 4096
#define MAXCAND 2048
__global__ __launch_bounds__(256) void topk_kernel(const float* __restrict__ x,
                                                   const float* __restrict__ ew,
                                                   const float* __restrict__ eb,
                                                   const float* __restrict__ db) {
    extern __shared__ unsigned int sh[];
    unsigned int* keys = sh;                         // 16384
    unsigned int* hist = sh + DD;                    // 4096
    unsigned long long* cand = (unsigned long long*)(hist + NBINS); // 2048

    __shared__ unsigned int part[256];
    __shared__ unsigned int s_thrbin, s_cnt;
    __shared__ unsigned long long wmax[8];
    __shared__ unsigned long long s_max;
    __shared__ float sval[NEX];
    __shared__ int   sidx[NEX];
    __shared__ double dv[NEX];

    int row = blockIdx.x;
    int b_  = row >> 3;
    int r_  = row & 7;
    int tid = threadIdx.x;
    const float* hp = g_h + (size_t)row * DD;

    for (int i = tid; i < NBINS; i += 256) hist[i] = 0;
    if (tid == 0) s_cnt = 0;
    __syncthreads();

    for (int i = tid; i < DD; i += 256) {
        unsigned int bb = __float_as_uint(hp[i]);
        unsigned int u = (bb & 0x80000000u) ? ~bb : (bb | 0x80000000u);
        keys[i] = u;
        atomicAdd(&hist[u >> 20], 1u);
    }
    __syncthreads();

    unsigned int psum = 0;
#pragma unroll
    for (int j = 0; j < 16; j++) psum += hist[tid * 16 + j];
    part[tid] = psum;
    __syncthreads();

    if (tid == 0) {
        unsigned int acc = 0;
        int seg = 255;
        for (; seg > 0; seg--) {
            if (acc + part[seg] >= THRC) break;
            acc += part[seg];
        }
        unsigned int a2 = acc;
        int T = seg * 16;
        for (int b2 = seg * 16 + 15; b2 >= seg * 16; b2--) {
            if (a2 + hist[b2] >= THRC) { T = b2; break; }
            a2 += hist[b2];
        }
        s_thrbin = (unsigned int)T;
    }
    __syncthreads();

    unsigned int T = s_thrbin;
    for (int i = tid; i < DD; i += 256) {
        if ((keys[i] >> 20) >= T) {
            unsigned int p = atomicAdd(&s_cnt, 1u);
            if (p < MAXCAND)
                cand[p] = ((unsigned long long)keys[i] << 32) |
                          (unsigned long long)(DD - 1 - i);   // ties -> lower i
        }
    }
    __syncthreads();

    unsigned int M = s_cnt < MAXCAND ? s_cnt : MAXCAND;
    int lane = tid & 31, warp = tid >> 5;

    for (int t = 0; t < NEX; t++) {
        unsigned long long lm = 0ull;
        for (unsigned int i = tid; i < M; i += 256) {
            unsigned long long v = cand[i];
            if (v > lm) lm = v;
        }
#pragma unroll
        for (int off = 16; off > 0; off >>= 1) {
            unsigned long long o = __shfl_xor_sync(0xffffffffu, lm, off);
            if (o > lm) lm = o;
        }
        if (lane == 0) wmax[warp] = lm;
        __syncthreads();
        if (tid == 0) {
            unsigned long long m = wmax[0];
#pragma unroll
            for (int w = 1; w < 8; w++) if (wmax[w] > m) m = wmax[w];
            s_max = m;
        }
        __syncthreads();
        unsigned long long m = s_max;
        for (unsigned int i = tid; i < M; i += 256)
            if (cand[i] == m) cand[i] = 0ull;
        if (tid == 0) {
            unsigned int u  = (unsigned int)(m >> 32);
            int idx = DD - 1 - (int)(m & 0xffffffffull);
            unsigned int fb = (u & 0x80000000u) ? (u & 0x7fffffffu) : ~u;
            sval[t] = __uint_as_float(fb);
            sidx[t] = idx;
        }
        __syncthreads();
    }

    // fp64 refinement of ALL NEX candidates (selection AND values become exact)
    double* xc = (double*)cand;   // cand region is free now; 2048 u64 >= 1024 dbl
    const float* xr  = x  + (size_t)b_ * (RR * CC) + (size_t)r_ * CC;
    const float* dbr = db + r_ * CC;
    const float* ewr = ew + (size_t)r_ * DD * CC;
    for (int c = tid; c < CC; c += 256)
        xc[c] = (double)xr[c] - (double)dbr[c];
    __syncthreads();

    for (int j = warp; j < NEX; j += 8) {
        int d = sidx[j];
        const float* wv = ewr + (size_t)d * CC;
        double a = 0.0;
        for (int c = lane; c < CC; c += 32)
            a += xc[c] * (double)wv[c];
#pragma unroll
        for (int off = 16; off > 0; off >>= 1)
            a += __shfl_down_sync(0xffffffffu, a, off);
        if (lane == 0)
            dv[j] = a + (double)eb[(size_t)r_ * DD + d];
    }
    __syncthreads();

    // re-rank (value desc, index asc) and emit top 32
    if (tid == 0) {
        for (int i = 1; i < NEX; i++) {
            double v = dv[i]; int id = sidx[i];
            int j = i - 1;
            while (j >= 0 && (dv[j] < v || (dv[j] == v && sidx[j] > id))) {
                dv[j + 1] = dv[j]; sidx[j + 1] = sidx[j]; j--;
            }
            dv[j + 1] = v; sidx[j + 1] = id;
        }
        for (int t = 0; t < KK; t++) {
            g_topv[row * KK + t] = fmaxf((float)dv[t], 0.f);
            g_topi[row * KK + t] = sidx[t];
        }
    }
}

// ---------------- kernel 4: sparse decode --------------------------------------
__global__ __launch_bounds__(256) void decode_kernel(const float* __restrict__ db,
                                                     float* __restrict__ out) {
    __shared__ float sv[KK];
    __shared__ int   si[KK];
    int b = blockIdx.x, r = blockIdx.y;
    int row = b * RR + r;
    int tid = threadIdx.x;
    if (tid < KK) {
        sv[tid] = g_topv[row * KK + tid];
        si[tid] = g_topi[row * KK + tid];
    }
    __syncthreads();

    const float* base = g_dwT + (size_t)r * DD * CC;
    float4 acc = *(const float4*)(db + r * CC + tid * 4);
#pragma unroll 8
    for (int t = 0; t < KK; t++) {
        float v = sv[t];
        float4 w = *(const float4*)(base + (size_t)si[t] * CC + tid * 4);
        acc.x += v * w.x;
        acc.y += v * w.y;
        acc.z += v * w.z;
        acc.w += v * w.w;
    }
    *(float4*)(out + (size_t)b * (RR * CC) + r * CC + tid * 4) = acc;
}

// ---------------- launch ---------------------------------------------------------
extern "C" void kernel_launch(void* const* d_in, const int* in_sizes, int n_in,
                              void* d_out, int out_size) {
    const float* x  = (const float*)d_in[0];
    const float* ew = (const float*)d_in[1];
    const float* eb = (const float*)d_in[2];
    const float* dw = (const float*)d_in[3];
    const float* db = (const float*)d_in[4];
    float* out = (float*)d_out;

    cudaFuncSetAttribute(topk_kernel,
                         cudaFuncAttributeMaxDynamicSharedMemorySize, 100352);
    cudaFuncSetAttribute(encode_gemm_mma,
                         cudaFuncAttributeMaxDynamicSharedMemorySize, STG * STAGE_B);

    conv_x<<<(BB * RR * CC / 4) / 256, 256>>>(x, db);
    conv_ew<<<(int)(((size_t)RR * DD * CC / 4) / 256), 256>>>(ew);
    transpose_dw<<<dim3(DD / 32, CC / 32, RR), dim3(32, 8)>>>(dw);
    // m fastest: 8 M-blocks sharing a B tile run concurrently (L2 reuse)
    encode_gemm_mma<<<dim3(BB / 128, DD / 128, RR), 256, STG * STAGE_B>>>(eb);
    topk_kernel<<<BB * RR, 256, (DD + NBINS) * 4 + MAXCAND * 8>>>(x, ew, eb, db);
    decode_kernel<<<dim3(BB, RR), 256>>>(db, out);
}

// round 5
// speedup vs baseline: 2.0367x; 1.0259x over previous
#include <cuda_runtime.h>
#include <cuda_bf16.h>
#include <cstdint>

// Problem constants
#define BB 1024
#define RR 8
#define CC 1024
#define DD 16384
#define KK 32
#define THRC 48
#define MAXC 256

// ---------------- device scratch ----------------------------------------------
__device__ __nv_bfloat16 g_h[(size_t)BB * RR * DD];   // 256 MB (ranking only)
__device__ float g_dwT[(size_t)RR * DD * CC];         // 512 MB
__device__ float g_topv[BB * RR * KK];
__device__ int   g_topi[BB * RR * KK];
__device__ __nv_bfloat16 g_xb[(size_t)BB * RR * CC];
__device__ __nv_bfloat16 g_ewb[(size_t)RR * DD * CC];

__device__ __forceinline__ uint32_t smem_u32(const void* p) {
    uint32_t a;
    asm("{ .reg .u64 t; cvta.to.shared.u64 t, %1; cvt.u32.u64 %0, t; }" : "=r"(a) : "l"(p));
    return a;
}

// ---------------- kernel 0a: x - db -> bf16 ------------------------------------
__global__ __launch_bounds__(256) void conv_x(const float* __restrict__ x,
                                              const float* __restrict__ db) {
    size_t i = (size_t)blockIdx.x * 256 + threadIdx.x;
    size_t e = i * 4;
    int c = (int)(e & (CC - 1));
    int r = (int)((e >> 10) & 7);
    float4 xv = ((const float4*)x)[i];
    float4 dv = *(const float4*)(db + r * CC + c);
    unsigned short h[4];
    h[0] = __bfloat16_as_ushort(__float2bfloat16(xv.x - dv.x));
    h[1] = __bfloat16_as_ushort(__float2bfloat16(xv.y - dv.y));
    h[2] = __bfloat16_as_ushort(__float2bfloat16(xv.z - dv.z));
    h[3] = __bfloat16_as_ushort(__float2bfloat16(xv.w - dv.w));
    uint2 u = {(uint32_t)h[0] | ((uint32_t)h[1] << 16),
               (uint32_t)h[2] | ((uint32_t)h[3] << 16)};
    ((uint2*)g_xb)[i] = u;
}

// ---------------- kernel 0b: ew -> bf16 -----------------------------------------
__global__ __launch_bounds__(256) void conv_ew(const float* __restrict__ ew) {
    size_t i = (size_t)blockIdx.x * 256 + threadIdx.x;
    float4 v = ((const float4*)ew)[i];
    unsigned short h[4];
    h[0] = __bfloat16_as_ushort(__float2bfloat16(v.x));
    h[1] = __bfloat16_as_ushort(__float2bfloat16(v.y));
    h[2] = __bfloat16_as_ushort(__float2bfloat16(v.z));
    h[3] = __bfloat16_as_ushort(__float2bfloat16(v.w));
    uint2 u = {(uint32_t)h[0] | ((uint32_t)h[1] << 16),
               (uint32_t)h[2] | ((uint32_t)h[3] << 16)};
    ((uint2*)g_ewb)[i] = u;
}

// ---------------- kernel 1: transpose decoder_w [R,C,D] -> [R,D,C] -------------
__global__ void transpose_dw(const float* __restrict__ dw) {
    __shared__ float tile[32][33];
    int r  = blockIdx.z;
    int d0 = blockIdx.x * 32;
    int c0 = blockIdx.y * 32;
    const float* src = dw   + (size_t)r * CC * DD;
    float*       dst = g_dwT + (size_t)r * DD * CC;
    int tx = threadIdx.x, ty = threadIdx.y;
#pragma unroll
    for (int i = 0; i < 32; i += 8)
        tile[ty + i][tx] = src[(size_t)(c0 + ty + i) * DD + d0 + tx];
    __syncthreads();
#pragma unroll
    for (int i = 0; i < 32; i += 8)
        dst[(size_t)(d0 + ty + i) * CC + c0 + tx] = tile[tx][ty + i];
}

// ---------------- kernel 2: encode GEMM via mma.sync (bf16, fp32 accum) --------
#define GBK 32
#define KT (CC / GBK)
#define STG 4
#define ATILE_B 8192
#define STAGE_B 16384

__device__ __forceinline__ void ldm_x4(uint32_t addr, uint32_t& r0, uint32_t& r1,
                                       uint32_t& r2, uint32_t& r3) {
    asm volatile("ldmatrix.sync.aligned.m8n8.x4.shared.b16 {%0,%1,%2,%3}, [%4];"
                 : "=r"(r0), "=r"(r1), "=r"(r2), "=r"(r3) : "r"(addr));
}
__device__ __forceinline__ void mma16816(float* c, uint32_t a0, uint32_t a1,
                                         uint32_t a2, uint32_t a3,
                                         uint32_t b0, uint32_t b1) {
    asm volatile(
        "mma.sync.aligned.m16n8k16.row.col.f32.bf16.bf16.f32 "
        "{%0,%1,%2,%3}, {%4,%5,%6,%7}, {%8,%9}, {%0,%1,%2,%3};"
        : "+f"(c[0]), "+f"(c[1]), "+f"(c[2]), "+f"(c[3])
        : "r"(a0), "r"(a1), "r"(a2), "r"(a3), "r"(b0), "r"(b1));
}

__global__ __launch_bounds__(256, 2) void encode_gemm_mma(const float* __restrict__ eb) {
    extern __shared__ char smem[];
    uint32_t sb = smem_u32(smem);

    int tid = threadIdx.x, lane = tid & 31, wid = tid >> 5;
    int warp_m = wid >> 2;
    int warp_n = wid & 3;
    int mBase = blockIdx.x * 128;
    int nBase = blockIdx.y * 128;
    int r     = blockIdx.z;

    const __nv_bfloat16* Bb = g_ewb + (size_t)r * DD * CC;

    uint32_t soff[4];
    const __nv_bfloat16* gbase[4];
#pragma unroll
    for (int i = 0; i < 4; i++) {
        int uid = tid + i * 256;
        int row = (uid & 511) >> 2;
        int u   = uid & 3;
        bool isA = uid < 512;
        soff[i] = (isA ? 0u : (uint32_t)ATILE_B) +
                  (uint32_t)(row * 64 + ((u ^ ((row >> 1) & 3)) << 4));
        gbase[i] = isA ? (g_xb + ((size_t)(mBase + row) * RR + r) * CC + u * 8)
                       : (Bb + (size_t)(nBase + row) * CC + u * 8);
    }

    auto issue_stage = [&](int kt, int s) {
        uint32_t sbase = sb + s * STAGE_B;
        int k0 = kt * GBK;
#pragma unroll
        for (int i = 0; i < 4; i++) {
            uint32_t sa = sbase + soff[i];
            const void* g = (const void*)(gbase[i] + k0);
            asm volatile("cp.async.cg.shared.global [%0], [%1], 16;"
                         :: "r"(sa), "l"(g));
        }
        asm volatile("cp.async.commit_group;");
    };

#pragma unroll
    for (int s = 0; s < STG - 1; s++) issue_stage(s, s);

    float acc[16][4];
#pragma unroll
    for (int i = 0; i < 16; i++)
#pragma unroll
        for (int j = 0; j < 4; j++) acc[i][j] = 0.f;

    int arow = warp_m * 64 + (lane & 15);
    int ab   = (lane >> 4) & 1;
    int nrow = warp_n * 32 + ((lane >> 4) << 3) + (lane & 7);
    int bb_  = (lane >> 3) & 1;

    for (int kt = 0; kt < KT; kt++) {
        asm volatile("cp.async.wait_group %0;" :: "n"(STG - 2));
        __syncthreads();
        if (kt + STG - 1 < KT) issue_stage(kt + STG - 1, (kt + STG - 1) & (STG - 1));
        else asm volatile("cp.async.commit_group;");

        uint32_t sA = sb + (kt & (STG - 1)) * STAGE_B;
        uint32_t sB = sA + ATILE_B;

#pragma unroll
        for (int ks = 0; ks < 2; ks++) {
            uint32_t bfr[8];
#pragma unroll
            for (int nfp = 0; nfp < 2; nfp++) {
                int rown = nrow + nfp * 16;
                int unit = ks * 2 + bb_;
                uint32_t addr = sB + rown * 64 + ((unit ^ ((rown >> 1) & 3)) << 4);
                ldm_x4(addr, bfr[nfp * 4 + 0], bfr[nfp * 4 + 1],
                             bfr[nfp * 4 + 2], bfr[nfp * 4 + 3]);
            }
#pragma unroll
            for (int mf = 0; mf < 4; mf++) {
                int rowm = arow + mf * 16;
                int unit = ks * 2 + ab;
                uint32_t addr = sA + rowm * 64 + ((unit ^ ((rowm >> 1) & 3)) << 4);
                uint32_t a0, a1, a2, a3;
                ldm_x4(addr, a0, a1, a2, a3);
#pragma unroll
                for (int nf = 0; nf < 4; nf++)
                    mma16816(acc[mf * 4 + nf], a0, a1, a2, a3,
                             bfr[nf * 2], bfr[nf * 2 + 1]);
            }
        }
        // single sync per iteration: next iteration's leading sync protects the
        // slot overwrite (it was consumed in the previous compute phase).
    }

    // epilogue: add eb, store bf16 h (ranking only)
    int trow = lane >> 2;
    int tcol = (lane & 3) * 2;
    const float* ebr = eb + (size_t)r * DD;
#pragma unroll
    for (int mf = 0; mf < 4; mf++) {
#pragma unroll
        for (int nf = 0; nf < 4; nf++) {
            int m = mBase + warp_m * 64 + mf * 16 + trow;
            int d = nBase + warp_n * 32 + nf * 8 + tcol;
            float2 ebv = *(const float2*)(ebr + d);
            __nv_bfloat16* h0 = g_h + (size_t)m * (RR * DD) + (size_t)r * DD + d;
            __nv_bfloat16* h1 = h0 + 8 * (size_t)(RR * DD);
            __nv_bfloat162 v0 = __floats2bfloat162_rn(acc[mf * 4 + nf][0] + ebv.x,
                                                      acc[mf * 4 + nf][1] + ebv.y);
            __nv_bfloat162 v1 = __floats2bfloat162_rn(acc[mf * 4 + nf][2] + ebv.x,
                                                      acc[mf * 4 + nf][3] + ebv.y);
            *(__nv_bfloat162*)h0 = v0;
            *(__nv_bfloat162*)h1 = v1;
        }
    }
}

// ---------------- kernel 3: topk = threshold-collect + fp64 refine + bitonic ---
// smem layout (dynamic, 52224 B):
//   [0, 32768)      u16 keys[16384]
//   [32768, 49152)  u32 hist[4096]     (reused as double xc[1024] after scan)
//   [49152, 50176)  u32 cidx[256]
//   [50176, 52224)  u64 skey[256]
__global__ __launch_bounds__(256) void topk_kernel(const float* __restrict__ x,
                                                   const float* __restrict__ ew,
                                                   const float* __restrict__ eb,
                                                   const float* __restrict__ db) {
    extern __shared__ char sm[];
    unsigned short* keys = (unsigned short*)sm;
    unsigned int*   hist = (unsigned int*)(sm + 32768);
    double*         xc   = (double*)(sm + 32768);
    unsigned int*   cidx = (unsigned int*)(sm + 49152);
    unsigned long long* skey = (unsigned long long*)(sm + 50176);

    __shared__ unsigned int part[256];
    __shared__ unsigned int s_thrbin, s_cnt;

    int row = blockIdx.x;
    int b_  = row >> 3;
    int r_  = row & 7;
    int tid = threadIdx.x;
    int lane = tid & 31, warp = tid >> 5;
    const __nv_bfloat16* hp = g_h + (size_t)row * DD;

    for (int i = tid; i < 4096; i += 256) hist[i] = 0;
    if (tid == 0) s_cnt = 0;
    __syncthreads();

    // keys from bf16 bits (order-preserving u16), histogram top-12 bits
    for (int i = tid; i < DD / 2; i += 256) {
        uint32_t v = ((const uint32_t*)hp)[i];
        unsigned short a = (unsigned short)(v & 0xFFFFu);
        unsigned short b = (unsigned short)(v >> 16);
        unsigned short ka = (a & 0x8000u) ? (unsigned short)~a : (unsigned short)(a | 0x8000u);
        unsigned short kb = (b & 0x8000u) ? (unsigned short)~b : (unsigned short)(b | 0x8000u);
        keys[2 * i]     = ka;
        keys[2 * i + 1] = kb;
        atomicAdd(&hist[ka >> 4], 1u);
        atomicAdd(&hist[kb >> 4], 1u);
    }
    __syncthreads();

    // smallest bin T with suffix count >= THRC
    unsigned int psum = 0;
#pragma unroll
    for (int j = 0; j < 16; j++) psum += hist[tid * 16 + j];
    part[tid] = psum;
    __syncthreads();

    if (tid == 0) {
        unsigned int acc = 0;
        int seg = 255;
        for (; seg > 0; seg--) {
            if (acc + part[seg] >= THRC) break;
            acc += part[seg];
        }
        unsigned int a2 = acc;
        int T = seg * 16;
        for (int b2 = seg * 16 + 15; b2 >= seg * 16; b2--) {
            if (a2 + hist[b2] >= THRC) { T = b2; break; }
            a2 += hist[b2];
        }
        s_thrbin = (unsigned int)T;
    }
    __syncthreads();

    // collect candidates; also stage xc (double) over the dead hist region
    unsigned int T = s_thrbin;
    const float* xr  = x  + (size_t)b_ * (RR * CC) + (size_t)r_ * CC;
    const float* dbr = db + r_ * CC;
    for (int c = tid; c < CC; c += 256)
        xc[c] = (double)xr[c] - (double)dbr[c];
    for (int i = tid; i < DD; i += 256) {
        if ((unsigned int)(keys[i] >> 4) >= T) {
            unsigned int p = atomicAdd(&s_cnt, 1u);
            if (p < MAXC) cidx[p] = (unsigned int)i;
        }
    }
    skey[tid] = 0ull;   // pad (smallest possible key)
    __syncthreads();

    unsigned int M = s_cnt < MAXC ? s_cnt : MAXC;
    const float* ewr = ew + (size_t)r_ * DD * CC;

    // fp64 refinement of every candidate; pack sortable key
    for (unsigned int j = warp; j < M; j += 8) {
        int d = (int)cidx[j];
        const float* wv = ewr + (size_t)d * CC;
        double a0 = 0.0, a1 = 0.0;
        for (int c = lane; c < CC; c += 64) {
            a0 += xc[c]      * (double)wv[c];
            a1 += xc[c + 32] * (double)wv[c + 32];
        }
        double a = a0 + a1;
#pragma unroll
        for (int off = 16; off > 0; off >>= 1)
            a += __shfl_down_sync(0xffffffffu, a, off);
        if (lane == 0) {
            double v = a + (double)eb[(size_t)r_ * DD + d];
            unsigned long long ub = (unsigned long long)__double_as_longlong(v);
            unsigned long long o = (ub >> 63) ? ~ub : (ub | 0x8000000000000000ull);
            o = (o & ~0x3FFFull) | (unsigned long long)(16383 - d);
            skey[j] = o;
        }
    }
    __syncthreads();

    // bitonic sort 256 keys ascending
    for (int k = 2; k <= 256; k <<= 1) {
        for (int j2 = k >> 1; j2 > 0; j2 >>= 1) {
            int i = tid;
            int ixj = i ^ j2;
            if (ixj > i) {
                unsigned long long ki = skey[i], kj = skey[ixj];
                bool up = ((i & k) == 0);
                if ((ki > kj) == up) { skey[i] = kj; skey[ixj] = ki; }
            }
            __syncthreads();
        }
    }

    // emit top 32 (largest keys at the end)
    if (tid < KK) {
        unsigned long long o = skey[255 - tid];
        int d = 16383 - (int)(o & 0x3FFFull);
        unsigned long long vb = o & ~0x3FFFull;
        unsigned long long ub = (vb >> 63) ? (vb & 0x7FFFFFFFFFFFFFFFull) : ~vb;
        double v = __longlong_as_double((long long)ub);
        g_topv[row * KK + tid] = fmaxf((float)v, 0.f);
        g_topi[row * KK + tid] = d;
    }
}

// ---------------- kernel 4: sparse decode --------------------------------------
__global__ __launch_bounds__(256) void decode_kernel(const float* __restrict__ db,
                                                     float* __restrict__ out) {
    __shared__ float sv[KK];
    __shared__ int   si[KK];
    int b = blockIdx.x, r = blockIdx.y;
    int row = b * RR + r;
    int tid = threadIdx.x;
    if (tid < KK) {
        sv[tid] = g_topv[row * KK + tid];
        si[tid] = g_topi[row * KK + tid];
    }
    __syncthreads();

    const float* base = g_dwT + (size_t)r * DD * CC;
    float4 acc = *(const float4*)(db + r * CC + tid * 4);
#pragma unroll 8
    for (int t = 0; t < KK; t++) {
        float v = sv[t];
        float4 w = *(const float4*)(base + (size_t)si[t] * CC + tid * 4);
        acc.x += v * w.x;
        acc.y += v * w.y;
        acc.z += v * w.z;
        acc.w += v * w.w;
    }
    *(float4*)(out + (size_t)b * (RR * CC) + r * CC + tid * 4) = acc;
}

// ---------------- launch ---------------------------------------------------------
extern "C" void kernel_launch(void* const* d_in, const int* in_sizes, int n_in,
                              void* d_out, int out_size) {
    const float* x  = (const float*)d_in[0];
    const float* ew = (const float*)d_in[1];
    const float* eb = (const float*)d_in[2];
    const float* dw = (const float*)d_in[3];
    const float* db = (const float*)d_in[4];
    float* out = (float*)d_out;

    cudaFuncSetAttribute(topk_kernel,
                         cudaFuncAttributeMaxDynamicSharedMemorySize, 52224);
    cudaFuncSetAttribute(encode_gemm_mma,
                         cudaFuncAttributeMaxDynamicSharedMemorySize, STG * STAGE_B);

    conv_x<<<(BB * RR * CC / 4) / 256, 256>>>(x, db);
    conv_ew<<<(int)(((size_t)RR * DD * CC / 4) / 256), 256>>>(ew);
    transpose_dw<<<dim3(DD / 32, CC / 32, RR), dim3(32, 8)>>>(dw);
    encode_gemm_mma<<<dim3(BB / 128, DD / 128, RR), 256, STG * STAGE_B>>>(eb);
    topk_kernel<<<BB * RR, 256, 52224>>>(x, ew, eb, db);
    decode_kernel<<<dim3(BB, RR), 256>>>(db, out);
}

// round 6
// speedup vs baseline: 2.7622x; 1.3562x over previous
#include <cuda_runtime.h>
#include <cuda_bf16.h>
#include <cstdint>

// Problem constants
#define BB 1024
#define RR 8
#define CC 1024
#define DD 16384
#define KK 32
#define THRC 48
#define MAXC 256

// ---------------- device scratch ----------------------------------------------
__device__ __nv_bfloat16 g_h[(size_t)BB * RR * DD];   // 256 MB (ranking only)
__device__ float g_dwT[(size_t)RR * DD * CC];         // 512 MB
__device__ float g_topv[BB * RR * KK];
__device__ int   g_topi[BB * RR * KK];
__device__ __nv_bfloat16 g_xb[(size_t)BB * RR * CC];
__device__ __nv_bfloat16 g_ewb[(size_t)RR * DD * CC];

__device__ __forceinline__ uint32_t smem_u32(const void* p) {
    uint32_t a;
    asm("{ .reg .u64 t; cvta.to.shared.u64 t, %1; cvt.u32.u64 %0, t; }" : "=r"(a) : "l"(p));
    return a;
}

// ---------------- kernel 0a: x - db -> bf16 ------------------------------------
__global__ __launch_bounds__(256) void conv_x(const float* __restrict__ x,
                                              const float* __restrict__ db) {
    size_t i = (size_t)blockIdx.x * 256 + threadIdx.x;
    size_t e = i * 4;
    int c = (int)(e & (CC - 1));
    int r = (int)((e >> 10) & 7);
    float4 xv = ((const float4*)x)[i];
    float4 dv = *(const float4*)(db + r * CC + c);
    unsigned short h[4];
    h[0] = __bfloat16_as_ushort(__float2bfloat16(xv.x - dv.x));
    h[1] = __bfloat16_as_ushort(__float2bfloat16(xv.y - dv.y));
    h[2] = __bfloat16_as_ushort(__float2bfloat16(xv.z - dv.z));
    h[3] = __bfloat16_as_ushort(__float2bfloat16(xv.w - dv.w));
    uint2 u = {(uint32_t)h[0] | ((uint32_t)h[1] << 16),
               (uint32_t)h[2] | ((uint32_t)h[3] << 16)};
    ((uint2*)g_xb)[i] = u;
}

// ---------------- kernel 0b: ew -> bf16 -----------------------------------------
__global__ __launch_bounds__(256) void conv_ew(const float* __restrict__ ew) {
    size_t i = (size_t)blockIdx.x * 256 + threadIdx.x;
    float4 v = ((const float4*)ew)[i];
    unsigned short h[4];
    h[0] = __bfloat16_as_ushort(__float2bfloat16(v.x));
    h[1] = __bfloat16_as_ushort(__float2bfloat16(v.y));
    h[2] = __bfloat16_as_ushort(__float2bfloat16(v.z));
    h[3] = __bfloat16_as_ushort(__float2bfloat16(v.w));
    uint2 u = {(uint32_t)h[0] | ((uint32_t)h[1] << 16),
               (uint32_t)h[2] | ((uint32_t)h[3] << 16)};
    ((uint2*)g_ewb)[i] = u;
}

// ---------------- kernel 1: transpose decoder_w [R,C,D] -> [R,D,C] -------------
__global__ void transpose_dw(const float* __restrict__ dw) {
    __shared__ float tile[32][33];
    int r  = blockIdx.z;
    int d0 = blockIdx.x * 32;
    int c0 = blockIdx.y * 32;
    const float* src = dw   + (size_t)r * CC * DD;
    float*       dst = g_dwT + (size_t)r * DD * CC;
    int tx = threadIdx.x, ty = threadIdx.y;
#pragma unroll
    for (int i = 0; i < 32; i += 8)
        tile[ty + i][tx] = src[(size_t)(c0 + ty + i) * DD + d0 + tx];
    __syncthreads();
#pragma unroll
    for (int i = 0; i < 32; i += 8)
        dst[(size_t)(d0 + ty + i) * CC + c0 + tx] = tile[tx][ty + i];
}

// ---------------- kernel 2: encode GEMM via mma.sync (bf16, fp32 accum) --------
#define GBK 32
#define KT (CC / GBK)
#define STG 4
#define ATILE_B 8192
#define STAGE_B 16384

__device__ __forceinline__ void ldm_x4(uint32_t addr, uint32_t& r0, uint32_t& r1,
                                       uint32_t& r2, uint32_t& r3) {
    asm volatile("ldmatrix.sync.aligned.m8n8.x4.shared.b16 {%0,%1,%2,%3}, [%4];"
                 : "=r"(r0), "=r"(r1), "=r"(r2), "=r"(r3) : "r"(addr));
}
__device__ __forceinline__ void mma16816(float* c, uint32_t a0, uint32_t a1,
                                         uint32_t a2, uint32_t a3,
                                         uint32_t b0, uint32_t b1) {
    asm volatile(
        "mma.sync.aligned.m16n8k16.row.col.f32.bf16.bf16.f32 "
        "{%0,%1,%2,%3}, {%4,%5,%6,%7}, {%8,%9}, {%0,%1,%2,%3};"
        : "+f"(c[0]), "+f"(c[1]), "+f"(c[2]), "+f"(c[3])
        : "r"(a0), "r"(a1), "r"(a2), "r"(a3), "r"(b0), "r"(b1));
}

__global__ __launch_bounds__(256, 2) void encode_gemm_mma(const float* __restrict__ eb) {
    extern __shared__ char smem[];
    uint32_t sb = smem_u32(smem);

    int tid = threadIdx.x, lane = tid & 31, wid = tid >> 5;
    int warp_m = wid >> 2;
    int warp_n = wid & 3;
    int mBase = blockIdx.x * 128;
    int nBase = blockIdx.y * 128;
    int r     = blockIdx.z;

    const __nv_bfloat16* Bb = g_ewb + (size_t)r * DD * CC;

    uint32_t soff[4];
    const __nv_bfloat16* gbase[4];
#pragma unroll
    for (int i = 0; i < 4; i++) {
        int uid = tid + i * 256;
        int row = (uid & 511) >> 2;
        int u   = uid & 3;
        bool isA = uid < 512;
        soff[i] = (isA ? 0u : (uint32_t)ATILE_B) +
                  (uint32_t)(row * 64 + ((u ^ ((row >> 1) & 3)) << 4));
        gbase[i] = isA ? (g_xb + ((size_t)(mBase + row) * RR + r) * CC + u * 8)
                       : (Bb + (size_t)(nBase + row) * CC + u * 8);
    }

    auto issue_stage = [&](int kt, int s) {
        uint32_t sbase = sb + s * STAGE_B;
        int k0 = kt * GBK;
#pragma unroll
        for (int i = 0; i < 4; i++) {
            uint32_t sa = sbase + soff[i];
            const void* g = (const void*)(gbase[i] + k0);
            asm volatile("cp.async.cg.shared.global [%0], [%1], 16;"
                         :: "r"(sa), "l"(g));
        }
        asm volatile("cp.async.commit_group;");
    };

#pragma unroll
    for (int s = 0; s < STG - 1; s++) issue_stage(s, s);

    float acc[16][4];
#pragma unroll
    for (int i = 0; i < 16; i++)
#pragma unroll
        for (int j = 0; j < 4; j++) acc[i][j] = 0.f;

    int arow = warp_m * 64 + (lane & 15);
    int ab   = (lane >> 4) & 1;
    int nrow = warp_n * 32 + ((lane >> 4) << 3) + (lane & 7);
    int bb_  = (lane >> 3) & 1;

    for (int kt = 0; kt < KT; kt++) {
        asm volatile("cp.async.wait_group %0;" :: "n"(STG - 2));
        __syncthreads();
        if (kt + STG - 1 < KT) issue_stage(kt + STG - 1, (kt + STG - 1) & (STG - 1));
        else asm volatile("cp.async.commit_group;");

        uint32_t sA = sb + (kt & (STG - 1)) * STAGE_B;
        uint32_t sB = sA + ATILE_B;

#pragma unroll
        for (int ks = 0; ks < 2; ks++) {
            uint32_t bfr[8];
#pragma unroll
            for (int nfp = 0; nfp < 2; nfp++) {
                int rown = nrow + nfp * 16;
                int unit = ks * 2 + bb_;
                uint32_t addr = sB + rown * 64 + ((unit ^ ((rown >> 1) & 3)) << 4);
                ldm_x4(addr, bfr[nfp * 4 + 0], bfr[nfp * 4 + 1],
                             bfr[nfp * 4 + 2], bfr[nfp * 4 + 3]);
            }
#pragma unroll
            for (int mf = 0; mf < 4; mf++) {
                int rowm = arow + mf * 16;
                int unit = ks * 2 + ab;
                uint32_t addr = sA + rowm * 64 + ((unit ^ ((rowm >> 1) & 3)) << 4);
                uint32_t a0, a1, a2, a3;
                ldm_x4(addr, a0, a1, a2, a3);
#pragma unroll
                for (int nf = 0; nf < 4; nf++)
                    mma16816(acc[mf * 4 + nf], a0, a1, a2, a3,
                             bfr[nf * 2], bfr[nf * 2 + 1]);
            }
        }
    }

    // epilogue: add eb, store bf16 h (ranking only)
    int trow = lane >> 2;
    int tcol = (lane & 3) * 2;
    const float* ebr = eb + (size_t)r * DD;
#pragma unroll
    for (int mf = 0; mf < 4; mf++) {
#pragma unroll
        for (int nf = 0; nf < 4; nf++) {
            int m = mBase + warp_m * 64 + mf * 16 + trow;
            int d = nBase + warp_n * 32 + nf * 8 + tcol;
            float2 ebv = *(const float2*)(ebr + d);
            __nv_bfloat16* h0 = g_h + (size_t)m * (RR * DD) + (size_t)r * DD + d;
            __nv_bfloat16* h1 = h0 + 8 * (size_t)(RR * DD);
            __nv_bfloat162 v0 = __floats2bfloat162_rn(acc[mf * 4 + nf][0] + ebv.x,
                                                      acc[mf * 4 + nf][1] + ebv.y);
            __nv_bfloat162 v1 = __floats2bfloat162_rn(acc[mf * 4 + nf][2] + ebv.x,
                                                      acc[mf * 4 + nf][3] + ebv.y);
            *(__nv_bfloat162*)h0 = v0;
            *(__nv_bfloat162*)h1 = v1;
        }
    }
}

// ---------------- kernel 3: topk = threshold-collect + compensated refine ------
// smem layout (dynamic, 52224 B):
//   [0, 32768)      u16 keys[16384]
//   [32768, 49152)  u32 hist[4096]     (reused as float xcf[1024] after scan)
//   [49152, 50176)  u32 cidx[256]
//   [50176, 52224)  u64 skey[256]
__global__ __launch_bounds__(256) void topk_kernel(const float* __restrict__ x,
                                                   const float* __restrict__ ew,
                                                   const float* __restrict__ eb,
                                                   const float* __restrict__ db) {
    extern __shared__ char sm[];
    unsigned short* keys = (unsigned short*)sm;
    unsigned int*   hist = (unsigned int*)(sm + 32768);
    float*          xcf  = (float*)(sm + 32768);
    unsigned int*   cidx = (unsigned int*)(sm + 49152);
    unsigned long long* skey = (unsigned long long*)(sm + 50176);

    __shared__ unsigned int part[256];
    __shared__ unsigned int s_thrbin, s_cnt;

    int row = blockIdx.x;
    int b_  = row >> 3;
    int r_  = row & 7;
    int tid = threadIdx.x;
    int lane = tid & 31, warp = tid >> 5;
    const __nv_bfloat16* hp = g_h + (size_t)row * DD;

    for (int i = tid; i < 4096; i += 256) hist[i] = 0;
    if (tid == 0) s_cnt = 0;
    __syncthreads();

    // keys from bf16 bits (order-preserving u16); warp-aggregated histogram
    for (int i = tid; i < DD / 2; i += 256) {
        uint32_t v = ((const uint32_t*)hp)[i];
        unsigned short a = (unsigned short)(v & 0xFFFFu);
        unsigned short b = (unsigned short)(v >> 16);
        unsigned short ka = (a & 0x8000u) ? (unsigned short)~a : (unsigned short)(a | 0x8000u);
        unsigned short kb = (b & 0x8000u) ? (unsigned short)~b : (unsigned short)(b | 0x8000u);
        keys[2 * i]     = ka;
        keys[2 * i + 1] = kb;
        unsigned int ba = (unsigned int)(ka >> 4);
        unsigned int bbb = (unsigned int)(kb >> 4);
        unsigned int m1 = __match_any_sync(0xffffffffu, ba);
        if ((m1 & ((1u << lane) - 1u)) == 0u) atomicAdd(&hist[ba], __popc(m1));
        unsigned int m2 = __match_any_sync(0xffffffffu, bbb);
        if ((m2 & ((1u << lane) - 1u)) == 0u) atomicAdd(&hist[bbb], __popc(m2));
    }
    __syncthreads();

    // per-thread partial (16 bins each), then warp-parallel suffix threshold
    unsigned int psum = 0;
#pragma unroll
    for (int j = 0; j < 16; j++) psum += hist[tid * 16 + j];
    part[tid] = psum;
    __syncthreads();

    if (warp == 0) {
        unsigned int pv[8], s8 = 0;
        int base = lane * 8;
#pragma unroll
        for (int j = 0; j < 8; j++) { pv[j] = part[base + j]; s8 += pv[j]; }
        // suffix sum across lanes (suf[l] = sum_{l' >= l} s8)
        unsigned int suf = s8;
#pragma unroll
        for (int off = 1; off < 32; off <<= 1) {
            unsigned int o = __shfl_down_sync(0xffffffffu, suf, off);
            if (lane + off < 32) suf += o;
        }
        unsigned int bal = __ballot_sync(0xffffffffu, suf >= THRC);
        int L = 31 - __clz((int)bal);     // highest lane with suffix >= THRC
        if (lane == L) {
            unsigned int acc = suf - s8;  // count in lanes above L
            int seg = base;
            for (int j = 7; j >= 0; j--) {
                if (acc + pv[j] >= THRC) { seg = base + j; break; }
                acc += pv[j];
            }
            int T = seg * 16;
            for (int b2 = seg * 16 + 15; b2 >= seg * 16; b2--) {
                if (acc + hist[b2] >= THRC) { T = b2; break; }
                acc += hist[b2];
            }
            s_thrbin = (unsigned int)T;
        }
    }
    __syncthreads();

    // collect candidates; stage xcf (fp32, matches reference x - db) over hist
    unsigned int T = s_thrbin;
    const float* xr  = x  + (size_t)b_ * (RR * CC) + (size_t)r_ * CC;
    const float* dbr = db + r_ * CC;
    for (int c = tid; c < CC; c += 256)
        xcf[c] = xr[c] - dbr[c];
    for (int i = tid; i < DD; i += 256) {
        if ((unsigned int)(keys[i] >> 4) >= T) {
            unsigned int p = atomicAdd(&s_cnt, 1u);
            if (p < MAXC) cidx[p] = (unsigned int)i;
        }
    }
    skey[tid] = 0ull;   // pad (smallest possible key)
    __syncthreads();

    unsigned int M = s_cnt < MAXC ? s_cnt : MAXC;
    const float* ewr = ew + (size_t)r_ * DD * CC;

    // compensated fp32 refinement (TwoProd + TwoSum; fp64-quality, FFMA-rate)
    for (unsigned int j = warp; j < M; j += 8) {
        int d = (int)cidx[j];
        const float* wv = ewr + (size_t)d * CC;
        float s = 0.f, comp = 0.f;
#pragma unroll 4
        for (int c = lane; c < CC; c += 32) {
            float xv = xcf[c];
            float wf = __ldg(wv + c);
            float p  = __fmul_rn(xv, wf);
            float e  = __fmaf_rn(xv, wf, -p);        // exact product residual
            float t  = __fadd_rn(s, p);              // TwoSum
            float z  = __fsub_rn(t, s);
            float lo = __fadd_rn(__fsub_rn(s, __fsub_rn(t, z)), __fsub_rn(p, z));
            s = t;
            comp = __fadd_rn(comp, __fadd_rn(lo, e));
        }
        double a = (double)s + (double)comp;
#pragma unroll
        for (int off = 16; off > 0; off >>= 1)
            a += __shfl_down_sync(0xffffffffu, a, off);
        if (lane == 0) {
            double v = a + (double)eb[(size_t)r_ * DD + d];
            unsigned long long ub = (unsigned long long)__double_as_longlong(v);
            unsigned long long o = (ub >> 63) ? ~ub : (ub | 0x8000000000000000ull);
            o = (o & ~0x3FFFull) | (unsigned long long)(16383 - d);
            skey[j] = o;
        }
    }
    __syncthreads();

    // bitonic sort 256 keys ascending
    for (int k = 2; k <= 256; k <<= 1) {
        for (int j2 = k >> 1; j2 > 0; j2 >>= 1) {
            int i = tid;
            int ixj = i ^ j2;
            if (ixj > i) {
                unsigned long long ki = skey[i], kj = skey[ixj];
                bool up = ((i & k) == 0);
                if ((ki > kj) == up) { skey[i] = kj; skey[ixj] = ki; }
            }
            __syncthreads();
        }
    }

    // emit top 32 (largest keys at the end)
    if (tid < KK) {
        unsigned long long o = skey[255 - tid];
        int d = 16383 - (int)(o & 0x3FFFull);
        unsigned long long vb = o & ~0x3FFFull;
        unsigned long long ub = (vb >> 63) ? (vb & 0x7FFFFFFFFFFFFFFFull) : ~vb;
        double v = __longlong_as_double((long long)ub);
        g_topv[row * KK + tid] = fmaxf((float)v, 0.f);
        g_topi[row * KK + tid] = d;
    }
}

// ---------------- kernel 4: sparse decode --------------------------------------
__global__ __launch_bounds__(256) void decode_kernel(const float* __restrict__ db,
                                                     float* __restrict__ out) {
    __shared__ float sv[KK];
    __shared__ int   si[KK];
    int b = blockIdx.x, r = blockIdx.y;
    int row = b * RR + r;
    int tid = threadIdx.x;
    if (tid < KK) {
        sv[tid] = g_topv[row * KK + tid];
        si[tid] = g_topi[row * KK + tid];
    }
    __syncthreads();

    const float* base = g_dwT + (size_t)r * DD * CC;
    float4 acc = *(const float4*)(db + r * CC + tid * 4);
#pragma unroll 8
    for (int t = 0; t < KK; t++) {
        float v = sv[t];
        float4 w = *(const float4*)(base + (size_t)si[t] * CC + tid * 4);
        acc.x += v * w.x;
        acc.y += v * w.y;
        acc.z += v * w.z;
        acc.w += v * w.w;
    }
    *(float4*)(out + (size_t)b * (RR * CC) + r * CC + tid * 4) = acc;
}

// ---------------- launch ---------------------------------------------------------
extern "C" void kernel_launch(void* const* d_in, const int* in_sizes, int n_in,
                              void* d_out, int out_size) {
    const float* x  = (const float*)d_in[0];
    const float* ew = (const float*)d_in[1];
    const float* eb = (const float*)d_in[2];
    const float* dw = (const float*)d_in[3];
    const float* db = (const float*)d_in[4];
    float* out = (float*)d_out;

    cudaFuncSetAttribute(topk_kernel,
                         cudaFuncAttributeMaxDynamicSharedMemorySize, 52224);
    cudaFuncSetAttribute(encode_gemm_mma,
                         cudaFuncAttributeMaxDynamicSharedMemorySize, STG * STAGE_B);

    conv_x<<<(BB * RR * CC / 4) / 256, 256>>>(x, db);
    conv_ew<<<(int)(((size_t)RR * DD * CC / 4) / 256), 256>>>(ew);
    transpose_dw<<<dim3(DD / 32, CC / 32, RR), dim3(32, 8)>>>(dw);
    encode_gemm_mma<<<dim3(BB / 128, DD / 128, RR), 256, STG * STAGE_B>>>(eb);
    topk_kernel<<<BB * RR, 256, 52224>>>(x, ew, eb, db);
    decode_kernel<<<dim3(BB, RR), 256>>>(db, out);
}

// round 7
// speedup vs baseline: 3.1010x; 1.1227x over previous
#include <cuda_runtime.h>
#include <cuda_bf16.h>
#include <cstdint>

// Problem constants
#define BB 1024
#define RR 8
#define CC 1024
#define DD 16384
#define KK 32
#define THRC 48
#define MAXC 256

// ---------------- device scratch ----------------------------------------------
__device__ __nv_bfloat16 g_h[(size_t)BB * RR * DD];   // 256 MB (ranking only)
__device__ float g_dwT[(size_t)RR * DD * CC];         // 512 MB
__device__ float g_topv[BB * RR * KK];
__device__ int   g_topi[BB * RR * KK];
__device__ __nv_bfloat16 g_xb[(size_t)BB * RR * CC];
__device__ __nv_bfloat16 g_ewb[(size_t)RR * DD * CC];
__device__ unsigned int g_cidx[(size_t)BB * RR * MAXC];   // 8 MB candidate idx
__device__ unsigned int g_ccnt[BB * RR];

__device__ __forceinline__ uint32_t smem_u32(const void* p) {
    uint32_t a;
    asm("{ .reg .u64 t; cvta.to.shared.u64 t, %1; cvt.u32.u64 %0, t; }" : "=r"(a) : "l"(p));
    return a;
}

// ---------------- kernel 0a: x - db -> bf16 ------------------------------------
__global__ __launch_bounds__(256) void conv_x(const float* __restrict__ x,
                                              const float* __restrict__ db) {
    size_t i = (size_t)blockIdx.x * 256 + threadIdx.x;
    size_t e = i * 4;
    int c = (int)(e & (CC - 1));
    int r = (int)((e >> 10) & 7);
    float4 xv = ((const float4*)x)[i];
    float4 dv = *(const float4*)(db + r * CC + c);
    unsigned short h[4];
    h[0] = __bfloat16_as_ushort(__float2bfloat16(xv.x - dv.x));
    h[1] = __bfloat16_as_ushort(__float2bfloat16(xv.y - dv.y));
    h[2] = __bfloat16_as_ushort(__float2bfloat16(xv.z - dv.z));
    h[3] = __bfloat16_as_ushort(__float2bfloat16(xv.w - dv.w));
    uint2 u = {(uint32_t)h[0] | ((uint32_t)h[1] << 16),
               (uint32_t)h[2] | ((uint32_t)h[3] << 16)};
    ((uint2*)g_xb)[i] = u;
}

// ---------------- kernel 0b: ew -> bf16 -----------------------------------------
__global__ __launch_bounds__(256) void conv_ew(const float* __restrict__ ew) {
    size_t i = (size_t)blockIdx.x * 256 + threadIdx.x;
    float4 v = ((const float4*)ew)[i];
    unsigned short h[4];
    h[0] = __bfloat16_as_ushort(__float2bfloat16(v.x));
    h[1] = __bfloat16_as_ushort(__float2bfloat16(v.y));
    h[2] = __bfloat16_as_ushort(__float2bfloat16(v.z));
    h[3] = __bfloat16_as_ushort(__float2bfloat16(v.w));
    uint2 u = {(uint32_t)h[0] | ((uint32_t)h[1] << 16),
               (uint32_t)h[2] | ((uint32_t)h[3] << 16)};
    ((uint2*)g_ewb)[i] = u;
}

// ---------------- kernel 1: transpose decoder_w [R,C,D] -> [R,D,C] -------------
__global__ void transpose_dw(const float* __restrict__ dw) {
    __shared__ float tile[32][33];
    int r  = blockIdx.z;
    int d0 = blockIdx.x * 32;
    int c0 = blockIdx.y * 32;
    const float* src = dw   + (size_t)r * CC * DD;
    float*       dst = g_dwT + (size_t)r * DD * CC;
    int tx = threadIdx.x, ty = threadIdx.y;
#pragma unroll
    for (int i = 0; i < 32; i += 8)
        tile[ty + i][tx] = src[(size_t)(c0 + ty + i) * DD + d0 + tx];
    __syncthreads();
#pragma unroll
    for (int i = 0; i < 32; i += 8)
        dst[(size_t)(d0 + ty + i) * CC + c0 + tx] = tile[tx][ty + i];
}

// ---------------- kernel 2: encode GEMM via mma.sync (bf16, fp32 accum) --------
#define GBK 32
#define KT (CC / GBK)
#define STG 4
#define ATILE_B 8192
#define STAGE_B 16384

__device__ __forceinline__ void ldm_x4(uint32_t addr, uint32_t& r0, uint32_t& r1,
                                       uint32_t& r2, uint32_t& r3) {
    asm volatile("ldmatrix.sync.aligned.m8n8.x4.shared.b16 {%0,%1,%2,%3}, [%4];"
                 : "=r"(r0), "=r"(r1), "=r"(r2), "=r"(r3) : "r"(addr));
}
__device__ __forceinline__ void mma16816(float* c, uint32_t a0, uint32_t a1,
                                         uint32_t a2, uint32_t a3,
                                         uint32_t b0, uint32_t b1) {
    asm volatile(
        "mma.sync.aligned.m16n8k16.row.col.f32.bf16.bf16.f32 "
        "{%0,%1,%2,%3}, {%4,%5,%6,%7}, {%8,%9}, {%0,%1,%2,%3};"
        : "+f"(c[0]), "+f"(c[1]), "+f"(c[2]), "+f"(c[3])
        : "r"(a0), "r"(a1), "r"(a2), "r"(a3), "r"(b0), "r"(b1));
}

__global__ __launch_bounds__(256, 2) void encode_gemm_mma(const float* __restrict__ eb) {
    extern __shared__ char smem[];
    uint32_t sb = smem_u32(smem);

    int tid = threadIdx.x, lane = tid & 31, wid = tid >> 5;
    int warp_m = wid >> 2;
    int warp_n = wid & 3;
    int mBase = blockIdx.x * 128;
    int nBase = blockIdx.y * 128;
    int r     = blockIdx.z;

    const __nv_bfloat16* Bb = g_ewb + (size_t)r * DD * CC;

    uint32_t soff[4];
    const __nv_bfloat16* gbase[4];
#pragma unroll
    for (int i = 0; i < 4; i++) {
        int uid = tid + i * 256;
        int row = (uid & 511) >> 2;
        int u   = uid & 3;
        bool isA = uid < 512;
        soff[i] = (isA ? 0u : (uint32_t)ATILE_B) +
                  (uint32_t)(row * 64 + ((u ^ ((row >> 1) & 3)) << 4));
        gbase[i] = isA ? (g_xb + ((size_t)(mBase + row) * RR + r) * CC + u * 8)
                       : (Bb + (size_t)(nBase + row) * CC + u * 8);
    }

    auto issue_stage = [&](int kt, int s) {
        uint32_t sbase = sb + s * STAGE_B;
        int k0 = kt * GBK;
#pragma unroll
        for (int i = 0; i < 4; i++) {
            uint32_t sa = sbase + soff[i];
            const void* g = (const void*)(gbase[i] + k0);
            asm volatile("cp.async.cg.shared.global [%0], [%1], 16;"
                         :: "r"(sa), "l"(g));
        }
        asm volatile("cp.async.commit_group;");
    };

#pragma unroll
    for (int s = 0; s < STG - 1; s++) issue_stage(s, s);

    float acc[16][4];
#pragma unroll
    for (int i = 0; i < 16; i++)
#pragma unroll
        for (int j = 0; j < 4; j++) acc[i][j] = 0.f;

    int arow = warp_m * 64 + (lane & 15);
    int ab   = (lane >> 4) & 1;
    int nrow = warp_n * 32 + ((lane >> 4) << 3) + (lane & 7);
    int bb_  = (lane >> 3) & 1;

    for (int kt = 0; kt < KT; kt++) {
        asm volatile("cp.async.wait_group %0;" :: "n"(STG - 2));
        __syncthreads();
        if (kt + STG - 1 < KT) issue_stage(kt + STG - 1, (kt + STG - 1) & (STG - 1));
        else asm volatile("cp.async.commit_group;");

        uint32_t sA = sb + (kt & (STG - 1)) * STAGE_B;
        uint32_t sB = sA + ATILE_B;

#pragma unroll
        for (int ks = 0; ks < 2; ks++) {
            uint32_t bfr[8];
#pragma unroll
            for (int nfp = 0; nfp < 2; nfp++) {
                int rown = nrow + nfp * 16;
                int unit = ks * 2 + bb_;
                uint32_t addr = sB + rown * 64 + ((unit ^ ((rown >> 1) & 3)) << 4);
                ldm_x4(addr, bfr[nfp * 4 + 0], bfr[nfp * 4 + 1],
                             bfr[nfp * 4 + 2], bfr[nfp * 4 + 3]);
            }
#pragma unroll
            for (int mf = 0; mf < 4; mf++) {
                int rowm = arow + mf * 16;
                int unit = ks * 2 + ab;
                uint32_t addr = sA + rowm * 64 + ((unit ^ ((rowm >> 1) & 3)) << 4);
                uint32_t a0, a1, a2, a3;
                ldm_x4(addr, a0, a1, a2, a3);
#pragma unroll
                for (int nf = 0; nf < 4; nf++)
                    mma16816(acc[mf * 4 + nf], a0, a1, a2, a3,
                             bfr[nf * 2], bfr[nf * 2 + 1]);
            }
        }
    }

    // epilogue: add eb, store bf16 h (ranking only)
    int trow = lane >> 2;
    int tcol = (lane & 3) * 2;
    const float* ebr = eb + (size_t)r * DD;
#pragma unroll
    for (int mf = 0; mf < 4; mf++) {
#pragma unroll
        for (int nf = 0; nf < 4; nf++) {
            int m = mBase + warp_m * 64 + mf * 16 + trow;
            int d = nBase + warp_n * 32 + nf * 8 + tcol;
            float2 ebv = *(const float2*)(ebr + d);
            __nv_bfloat16* h0 = g_h + (size_t)m * (RR * DD) + (size_t)r * DD + d;
            __nv_bfloat16* h1 = h0 + 8 * (size_t)(RR * DD);
            __nv_bfloat162 v0 = __floats2bfloat162_rn(acc[mf * 4 + nf][0] + ebv.x,
                                                      acc[mf * 4 + nf][1] + ebv.y);
            __nv_bfloat162 v1 = __floats2bfloat162_rn(acc[mf * 4 + nf][2] + ebv.x,
                                                      acc[mf * 4 + nf][3] + ebv.y);
            *(__nv_bfloat162*)h0 = v0;
            *(__nv_bfloat162*)h1 = v1;
        }
    }
}

// ---------------- kernel 3a: candidate selection (histogram threshold) ---------
__global__ __launch_bounds__(256) void topk_select() {
    __shared__ unsigned int hist[4096];
    __shared__ unsigned int part[256];
    __shared__ unsigned int s_thrbin, s_cnt;

    int row = blockIdx.x;
    int tid = threadIdx.x;
    int lane = tid & 31, warp = tid >> 5;
    const __nv_bfloat16* hp = g_h + (size_t)row * DD;

    for (int i = tid; i < 4096; i += 256) hist[i] = 0;
    if (tid == 0) s_cnt = 0;
    __syncthreads();

    // pass 1: order-preserving u16 keys; warp-aggregated histogram (12-bit bins)
    for (int i = tid; i < DD / 2; i += 256) {
        uint32_t v = ((const uint32_t*)hp)[i];
        unsigned short a = (unsigned short)(v & 0xFFFFu);
        unsigned short b = (unsigned short)(v >> 16);
        unsigned short ka = (a & 0x8000u) ? (unsigned short)~a : (unsigned short)(a | 0x8000u);
        unsigned short kb = (b & 0x8000u) ? (unsigned short)~b : (unsigned short)(b | 0x8000u);
        unsigned int ba = (unsigned int)(ka >> 4);
        unsigned int bbb = (unsigned int)(kb >> 4);
        unsigned int m1 = __match_any_sync(0xffffffffu, ba);
        if ((m1 & ((1u << lane) - 1u)) == 0u) atomicAdd(&hist[ba], __popc(m1));
        unsigned int m2 = __match_any_sync(0xffffffffu, bbb);
        if ((m2 & ((1u << lane) - 1u)) == 0u) atomicAdd(&hist[bbb], __popc(m2));
    }
    __syncthreads();

    unsigned int psum = 0;
#pragma unroll
    for (int j = 0; j < 16; j++) psum += hist[tid * 16 + j];
    part[tid] = psum;
    __syncthreads();

    if (warp == 0) {
        unsigned int pv[8], s8 = 0;
        int base = lane * 8;
#pragma unroll
        for (int j = 0; j < 8; j++) { pv[j] = part[base + j]; s8 += pv[j]; }
        unsigned int suf = s8;
#pragma unroll
        for (int off = 1; off < 32; off <<= 1) {
            unsigned int o = __shfl_down_sync(0xffffffffu, suf, off);
            if (lane + off < 32) suf += o;
        }
        unsigned int bal = __ballot_sync(0xffffffffu, suf >= THRC);
        int L = 31 - __clz((int)bal);
        if (lane == L) {
            unsigned int acc = suf - s8;
            int seg = base;
            for (int j = 7; j >= 0; j--) {
                if (acc + pv[j] >= THRC) { seg = base + j; break; }
                acc += pv[j];
            }
            int T = seg * 16;
            for (int b2 = seg * 16 + 15; b2 >= seg * 16; b2--) {
                if (acc + hist[b2] >= THRC) { T = b2; break; }
                acc += hist[b2];
            }
            s_thrbin = (unsigned int)T;
        }
    }
    __syncthreads();

    // pass 2: recompute keys from L2-resident h row, collect candidate indices
    unsigned int T = s_thrbin;
    unsigned int* crow = g_cidx + (size_t)row * MAXC;
    for (int i = tid; i < DD / 2; i += 256) {
        uint32_t v = ((const uint32_t*)hp)[i];
        unsigned short a = (unsigned short)(v & 0xFFFFu);
        unsigned short b = (unsigned short)(v >> 16);
        unsigned short ka = (a & 0x8000u) ? (unsigned short)~a : (unsigned short)(a | 0x8000u);
        unsigned short kb = (b & 0x8000u) ? (unsigned short)~b : (unsigned short)(b | 0x8000u);
        if ((unsigned int)(ka >> 4) >= T) {
            unsigned int p = atomicAdd(&s_cnt, 1u);
            if (p < MAXC) crow[p] = (unsigned int)(2 * i);
        }
        if ((unsigned int)(kb >> 4) >= T) {
            unsigned int p = atomicAdd(&s_cnt, 1u);
            if (p < MAXC) crow[p] = (unsigned int)(2 * i + 1);
        }
    }
    __syncthreads();
    if (tid == 0) g_ccnt[row] = s_cnt < MAXC ? s_cnt : MAXC;
}

// ---------------- kernel 3b: compensated refine + rank (high occupancy) --------
__global__ __launch_bounds__(256) void topk_refine(const float* __restrict__ x,
                                                   const float* __restrict__ ew,
                                                   const float* __restrict__ eb,
                                                   const float* __restrict__ db) {
    __shared__ float xcf[CC];
    __shared__ unsigned long long skey[256];

    int row = blockIdx.x;
    int b_  = row >> 3;
    int r_  = row & 7;
    int tid = threadIdx.x;
    int lane = tid & 31, warp = tid >> 5;

    const float* xr  = x  + (size_t)b_ * (RR * CC) + (size_t)r_ * CC;
    const float* dbr = db + r_ * CC;
    for (int c = tid; c < CC; c += 256)
        xcf[c] = xr[c] - dbr[c];
    skey[tid] = 0ull;
    __syncthreads();

    unsigned int M = g_ccnt[row];
    const unsigned int* crow = g_cidx + (size_t)row * MAXC;
    const float* ewr = ew + (size_t)r_ * DD * CC;

    // compensated fp32 dot per candidate (TwoProd + TwoSum), warp-parallel
    for (unsigned int j = warp; j < M; j += 8) {
        int d = (int)crow[j];
        const float* wv = ewr + (size_t)d * CC;
        float s = 0.f, comp = 0.f;
#pragma unroll 4
        for (int c = lane; c < CC; c += 32) {
            float xv = xcf[c];
            float wf = __ldg(wv + c);
            float p  = __fmul_rn(xv, wf);
            float e  = __fmaf_rn(xv, wf, -p);
            float t  = __fadd_rn(s, p);
            float z  = __fsub_rn(t, s);
            float lo = __fadd_rn(__fsub_rn(s, __fsub_rn(t, z)), __fsub_rn(p, z));
            s = t;
            comp = __fadd_rn(comp, __fadd_rn(lo, e));
        }
        double a = (double)s + (double)comp;
#pragma unroll
        for (int off = 16; off > 0; off >>= 1)
            a += __shfl_down_sync(0xffffffffu, a, off);
        if (lane == 0) {
            double v = a + (double)eb[(size_t)r_ * DD + d];
            unsigned long long ub = (unsigned long long)__double_as_longlong(v);
            unsigned long long o = (ub >> 63) ? ~ub : (ub | 0x8000000000000000ull);
            o = (o & ~0x3FFFull) | (unsigned long long)(16383 - d);
            skey[j] = o;
        }
    }
    __syncthreads();

    // bitonic sort 256 keys ascending
    for (int k = 2; k <= 256; k <<= 1) {
        for (int j2 = k >> 1; j2 > 0; j2 >>= 1) {
            int i = tid;
            int ixj = i ^ j2;
            if (ixj > i) {
                unsigned long long ki = skey[i], kj = skey[ixj];
                bool up = ((i & k) == 0);
                if ((ki > kj) == up) { skey[i] = kj; skey[ixj] = ki; }
            }
            __syncthreads();
        }
    }

    if (tid < KK) {
        unsigned long long o = skey[255 - tid];
        int d = 16383 - (int)(o & 0x3FFFull);
        unsigned long long vb = o & ~0x3FFFull;
        unsigned long long ub = (vb >> 63) ? (vb & 0x7FFFFFFFFFFFFFFFull) : ~vb;
        double v = __longlong_as_double((long long)ub);
        g_topv[row * KK + tid] = fmaxf((float)v, 0.f);
        g_topi[row * KK + tid] = d;
    }
}

// ---------------- kernel 4: sparse decode --------------------------------------
__global__ __launch_bounds__(256) void decode_kernel(const float* __restrict__ db,
                                                     float* __restrict__ out) {
    __shared__ float sv[KK];
    __shared__ int   si[KK];
    int b = blockIdx.x, r = blockIdx.y;
    int row = b * RR + r;
    int tid = threadIdx.x;
    if (tid < KK) {
        sv[tid] = g_topv[row * KK + tid];
        si[tid] = g_topi[row * KK + tid];
    }
    __syncthreads();

    const float* base = g_dwT + (size_t)r * DD * CC;
    float4 acc = *(const float4*)(db + r * CC + tid * 4);
#pragma unroll 8
    for (int t = 0; t < KK; t++) {
        float v = sv[t];
        float4 w = *(const float4*)(base + (size_t)si[t] * CC + tid * 4);
        acc.x += v * w.x;
        acc.y += v * w.y;
        acc.z += v * w.z;
        acc.w += v * w.w;
    }
    *(float4*)(out + (size_t)b * (RR * CC) + r * CC + tid * 4) = acc;
}

// ---------------- launch ---------------------------------------------------------
extern "C" void kernel_launch(void* const* d_in, const int* in_sizes, int n_in,
                              void* d_out, int out_size) {
    const float* x  = (const float*)d_in[0];
    const float* ew = (const float*)d_in[1];
    const float* eb = (const float*)d_in[2];
    const float* dw = (const float*)d_in[3];
    const float* db = (const float*)d_in[4];
    float* out = (float*)d_out;

    cudaFuncSetAttribute(encode_gemm_mma,
                         cudaFuncAttributeMaxDynamicSharedMemorySize, STG * STAGE_B);

    conv_x<<<(BB * RR * CC / 4) / 256, 256>>>(x, db);
    conv_ew<<<(int)(((size_t)RR * DD * CC / 4) / 256), 256>>>(ew);
    transpose_dw<<<dim3(DD / 32, CC / 32, RR), dim3(32, 8)>>>(dw);
    encode_gemm_mma<<<dim3(BB / 128, DD / 128, RR), 256, STG * STAGE_B>>>(eb);
    topk_select<<<BB * RR, 256>>>();
    topk_refine<<<BB * RR, 256>>>(x, ew, eb, db);
    decode_kernel<<<dim3(BB, RR), 256>>>(db, out);
}